// round 4
// baseline (speedup 1.0000x reference)
#include <cuda_runtime.h>
#include <cuda_bf16.h>
#include <math.h>
#include <stdint.h>

// ---------------------------------------------------------------------------
// Problem constants
//   b=16, s=512, d=2048, H=16 heads, hd=128, G=4 kv groups, P=4 heads/group
// ---------------------------------------------------------------------------
#define BB 16
#define SS 512
#define DD 2048
#define NH 16
#define HD 128
#define NG 4
#define MROWS (BB * SS)          // 8192

// Scratch (device globals: allocation-free rule)
__device__ float g_q[MROWS * DD];          // (b,s,H,hd) = 64MB
__device__ float g_k[MROWS * NG * HD];     // (b,s,G,hd) = 16MB
__device__ float g_v[MROWS * NG * HD];     // 16MB
__device__ float g_ctx[MROWS * DD];        // 64MB

// ---------------------------------------------------------------------------
// tf32 helpers
// ---------------------------------------------------------------------------
__device__ __forceinline__ uint32_t f2tf32(float f) {
    uint32_t u;
    asm("cvt.rna.tf32.f32 %0, %1;" : "=r"(u) : "f"(f));
    return u;
}

__device__ __forceinline__ void mma1688(float* c, const uint32_t* a, const uint32_t* b) {
    asm volatile(
        "mma.sync.aligned.m16n8k8.row.col.f32.tf32.tf32.f32 "
        "{%0,%1,%2,%3}, {%4,%5,%6,%7}, {%8,%9}, {%0,%1,%2,%3};"
        : "+f"(c[0]), "+f"(c[1]), "+f"(c[2]), "+f"(c[3])
        : "r"(a[0]), "r"(a[1]), "r"(a[2]), "r"(a[3]), "r"(b[0]), "r"(b[1]));
}

// ---------------------------------------------------------------------------
// TF32 tensor-core GEMM: C[M,N] = A[M,K] @ B[K,N] + bias[N]  (row-major fp32)
// Block tile 128x128, BK=16, 256 threads (8 warps, 2x4 warp grid),
// warp tile 64x32 via m16n8k8 tf32 mma. Smem tiles are stored in a
// fragment-permuted layout so fragment fetches are single conflict-free
// LDS.128 (A) / LDS.64 (B). Double-buffered, register-prefetched.
// M % 128 == 0, N % 128 == 0, K % 16 == 0 (true for all 4 calls).
// ---------------------------------------------------------------------------
__global__ __launch_bounds__(256, 1)
void mm_tf32_kernel(const float* __restrict__ A, const float* __restrict__ B,
                    const float* __restrict__ bias, float* __restrict__ C,
                    int M, int N, int K)
{
    // per buffer: A 128x16 = 2048 u32 (8KB), B 16x128 = 2048 u32 (8KB)
    __shared__ uint32_t As[2][2048];
    __shared__ uint32_t Bs[2][2048];

    const int tid  = threadIdx.x;
    const int lane = tid & 31;
    const int wid  = tid >> 5;
    const int wm   = wid >> 2;        // 0..1  (M direction, 64 rows each)
    const int wn   = wid & 3;         // 0..3  (N direction, 32 cols each)
    const int g_c  = lane >> 2;       // mma groupID
    const int t_c  = lane & 3;        // mma threadID-in-group
    const int m0   = blockIdx.y << 7;
    const int n0   = blockIdx.x << 7;

    // ---- global-load mapping -------------------------------------------
    // A tile 128 rows x 16 cols: thread loads float4 at (row=tid>>2, col=(tid&3)*4)
    // and the same at row+64.
    const int a_r = tid >> 2;              // 0..63
    const int a_c = (tid & 3) << 2;        // 0,4,8,12
    // B tile 16 rows x 128 cols: float4 at (row=tid>>5, col=(tid&31)*4) and row+8.
    const int b_r = tid >> 5;              // 0..7
    const int b_c = (tid & 31) << 2;       // 0..124

    const float* Ap = A + (size_t)(m0 + a_r) * K + a_c;
    const float* Bp = B + (size_t)b_r * N + n0 + b_c;

    // ---- fragment-permuted smem scatter bases (constant per thread) ----
    // A element (row, k): mt=row>>4, g=row&7, rbit=(row>>3)&1,
    //   kc=k>>3, tig=k&3, hi=(k>>2)&1
    //   idx = (kc*8+mt)*128 + (g*4+tig)*4 + rbit + 2*hi          (j stride 4)
    {
    }
    const int a_kc  = a_c >> 3;
    const int a_hi  = (a_c >> 2) & 1;
    const int a_mt  = a_r >> 4;
    const int a_g   = a_r & 7;
    const int a_rb  = (a_r >> 3) & 1;
    const int a_base = (a_kc * 8 + a_mt) * 128 + (a_g * 4) * 4 + a_rb + 2 * a_hi;
    // row+64 -> mt += 4 -> +512
    // B element (k, n): kc=k>>3, tig=k&3, hi=(k>>2)&1, nt=n>>3, g=n&7
    //   idx = (kc*16+nt)*64 + (g*4+tig)*2 + hi                   (j stride 8)
    const int b_tig = b_r & 3;
    const int b_hi  = (b_r >> 2) & 1;
    const int b_nt  = b_c >> 3;
    const int b_g0  = b_c & 7;             // 0 or 4
    const int b_base = (b_nt) * 64 + (b_g0 * 4 + b_tig) * 2 + b_hi;  // kc=0 half
    // k+8 -> kc=1 -> +1024

    float acc[4][4][4];
#pragma unroll
    for (int i = 0; i < 4; ++i)
#pragma unroll
        for (int j = 0; j < 4; ++j)
#pragma unroll
            for (int r = 0; r < 4; ++r) acc[i][j][r] = 0.f;

    // ---- prologue: tile 0 ----------------------------------------------
    {
        float4 pa0 = *(const float4*)(Ap);
        float4 pa1 = *(const float4*)(Ap + 64 * K);
        float4 pb0 = *(const float4*)(Bp);
        float4 pb1 = *(const float4*)(Bp + 8 * N);
        As[0][a_base + 0]        = f2tf32(pa0.x);
        As[0][a_base + 4]        = f2tf32(pa0.y);
        As[0][a_base + 8]        = f2tf32(pa0.z);
        As[0][a_base + 12]       = f2tf32(pa0.w);
        As[0][a_base + 512 + 0]  = f2tf32(pa1.x);
        As[0][a_base + 512 + 4]  = f2tf32(pa1.y);
        As[0][a_base + 512 + 8]  = f2tf32(pa1.z);
        As[0][a_base + 512 + 12] = f2tf32(pa1.w);
        Bs[0][b_base + 0]         = f2tf32(pb0.x);
        Bs[0][b_base + 8]         = f2tf32(pb0.y);
        Bs[0][b_base + 16]        = f2tf32(pb0.z);
        Bs[0][b_base + 24]        = f2tf32(pb0.w);
        Bs[0][b_base + 1024 + 0]  = f2tf32(pb1.x);
        Bs[0][b_base + 1024 + 8]  = f2tf32(pb1.y);
        Bs[0][b_base + 1024 + 16] = f2tf32(pb1.z);
        Bs[0][b_base + 1024 + 24] = f2tf32(pb1.w);
    }
    __syncthreads();

    const int ntiles = K >> 4;
    int buf = 0;
    for (int t = 0; t < ntiles; ++t) {
        float4 pa0, pa1, pb0, pb1;
        const bool pf = (t + 1 < ntiles);
        if (pf) {
            const float* Ap2 = Ap + ((t + 1) << 4);
            const float* Bp2 = Bp + (size_t)((t + 1) << 4) * N;
            pa0 = *(const float4*)(Ap2);
            pa1 = *(const float4*)(Ap2 + 64 * K);
            pb0 = *(const float4*)(Bp2);
            pb1 = *(const float4*)(Bp2 + 8 * N);
        }

        // ---- compute on buf: 2 k-chunks of 8 ----
#pragma unroll
        for (int kc = 0; kc < 2; ++kc) {
            uint32_t af[4][4];
            uint32_t bf[4][2];
#pragma unroll
            for (int i = 0; i < 4; ++i) {
                const int mt = wm * 4 + i;
                *(uint4*)af[i] = *(const uint4*)&As[buf][(kc * 8 + mt) * 128 + lane * 4];
            }
#pragma unroll
            for (int j = 0; j < 4; ++j) {
                const int nt = wn * 4 + j;
                *(uint2*)bf[j] = *(const uint2*)&Bs[buf][(kc * 16 + nt) * 64 + lane * 2];
            }
#pragma unroll
            for (int i = 0; i < 4; ++i)
#pragma unroll
                for (int j = 0; j < 4; ++j)
                    mma1688(acc[i][j], af[i], bf[j]);
        }

        if (pf) {
            const int nb = buf ^ 1;
            As[nb][a_base + 0]        = f2tf32(pa0.x);
            As[nb][a_base + 4]        = f2tf32(pa0.y);
            As[nb][a_base + 8]        = f2tf32(pa0.z);
            As[nb][a_base + 12]       = f2tf32(pa0.w);
            As[nb][a_base + 512 + 0]  = f2tf32(pa1.x);
            As[nb][a_base + 512 + 4]  = f2tf32(pa1.y);
            As[nb][a_base + 512 + 8]  = f2tf32(pa1.z);
            As[nb][a_base + 512 + 12] = f2tf32(pa1.w);
            Bs[nb][b_base + 0]         = f2tf32(pb0.x);
            Bs[nb][b_base + 8]         = f2tf32(pb0.y);
            Bs[nb][b_base + 16]        = f2tf32(pb0.z);
            Bs[nb][b_base + 24]        = f2tf32(pb0.w);
            Bs[nb][b_base + 1024 + 0]  = f2tf32(pb1.x);
            Bs[nb][b_base + 1024 + 8]  = f2tf32(pb1.y);
            Bs[nb][b_base + 1024 + 16] = f2tf32(pb1.z);
            Bs[nb][b_base + 1024 + 24] = f2tf32(pb1.w);
            __syncthreads();
            buf = nb;
        }
    }

    // ---- epilogue: bias + store ----------------------------------------
#pragma unroll
    for (int j = 0; j < 4; ++j) {
        const int col = n0 + wn * 32 + j * 8 + t_c * 2;
        const float2 bs = *(const float2*)&bias[col];
#pragma unroll
        for (int i = 0; i < 4; ++i) {
            const int row = m0 + wm * 64 + i * 16 + g_c;
            float2 v0, v1;
            v0.x = acc[i][j][0] + bs.x; v0.y = acc[i][j][1] + bs.y;
            v1.x = acc[i][j][2] + bs.x; v1.y = acc[i][j][3] + bs.y;
            *(float2*)&C[(size_t)row * N + col]       = v0;
            *(float2*)&C[(size_t)(row + 8) * N + col] = v1;
        }
    }
}

// ---------------------------------------------------------------------------
// RMSNorm + RoPE, fused. X viewed as [B*S*nh][128] rows.
// One warp per row (4 floats/lane). extra = post-rope scalar (1/128 for q).
// ---------------------------------------------------------------------------
__global__ __launch_bounds__(256)
void norm_rope_kernel(float* __restrict__ X, const float* __restrict__ scale,
                      int nh, float extra)
{
    const int warp = threadIdx.x >> 5;
    const int lane = threadIdx.x & 31;
    const int row  = blockIdx.x * 8 + warp;
    const int t    = (row / nh) & (SS - 1);

    float* p = X + (size_t)row * HD + lane * 4;
    float4 v = *(float4*)p;

    float ss = v.x * v.x + v.y * v.y + v.z * v.z + v.w * v.w;
#pragma unroll
    for (int o = 16; o; o >>= 1) ss += __shfl_xor_sync(0xffffffffu, ss, o);
    const float r = rsqrtf(ss * (1.0f / 128.0f) + 1e-6f);

    float4 sc = *(const float4*)(scale + lane * 4);
    float y0 = v.x * r * sc.x;
    float y1 = v.y * r * sc.y;
    float y2 = v.z * r * sc.z;
    float y3 = v.w * r * sc.w;

    const int i0 = lane * 2;
    const float LN1E4 = 9.2103403719761836f;  // ln(10000)
    float f0 = expf(-((float)(2 * i0)     * (1.0f / 128.0f)) * LN1E4);
    float f1 = expf(-((float)(2 * i0 + 2) * (1.0f / 128.0f)) * LN1E4);
    float s0, c0, s1, c1;
    sincosf((float)t * f0, &s0, &c0);
    sincosf((float)t * f1, &s1, &c1);

    float4 o;
    o.x = (y0 * c0 - y1 * s0) * extra;
    o.y = (y0 * s0 + y1 * c0) * extra;
    o.z = (y2 * c1 - y3 * s1) * extra;
    o.w = (y2 * s1 + y3 * c1) * extra;
    *(float4*)p = o;
}

// ---------------------------------------------------------------------------
// Causal flash attention, fp32 (unchanged from R1 passing version).
// ---------------------------------------------------------------------------
#define QS_LD 129
#define PS_LD 68
#define ATTN_SMEM ((2 * 64 * QS_LD + 64 * PS_LD) * 4)   // 83456 bytes

__global__ __launch_bounds__(256)
void attn_kernel(const float* __restrict__ Q, const float* __restrict__ Kg,
                 const float* __restrict__ Vg, float* __restrict__ ctx)
{
    extern __shared__ float sm[];
    float* Qs = sm;                       // [64][129]
    float* Ks = sm + 64 * QS_LD;          // [64][129], reused for V
    float* Ps = sm + 2 * 64 * QS_LD;      // [64][68]

    const int tid = threadIdx.x;
    const int tx  = tid & 15;
    const int ty  = tid >> 4;
    const int q0  = blockIdx.x << 6;
    const int h   = blockIdx.y;
    const int b   = blockIdx.z;
    const int g   = h >> 2;

    for (int f = tid; f < 2048; f += 256) {
        const int r = f >> 5, c = (f & 31) << 2;
        float4 v = *(const float4*)(Q + ((size_t)((b * SS + q0 + r) * NH + h)) * HD + c);
        float* d = Qs + r * QS_LD + c;
        d[0] = v.x; d[1] = v.y; d[2] = v.z; d[3] = v.w;
    }

    float m_run[4], l_run[4], Ob[4][8];
#pragma unroll
    for (int i = 0; i < 4; ++i) {
        m_run[i] = -1e30f; l_run[i] = 0.f;
#pragma unroll
        for (int c = 0; c < 8; ++c) Ob[i][c] = 0.f;
    }

    const float* q_r0 = Qs + (ty * 4 + 0) * QS_LD;
    const float* q_r1 = Qs + (ty * 4 + 1) * QS_LD;
    const float* q_r2 = Qs + (ty * 4 + 2) * QS_LD;
    const float* q_r3 = Qs + (ty * 4 + 3) * QS_LD;
    const float* k_r0 = Ks + (tx * 4 + 0) * QS_LD;
    const float* k_r1 = Ks + (tx * 4 + 1) * QS_LD;
    const float* k_r2 = Ks + (tx * 4 + 2) * QS_LD;
    const float* k_r3 = Ks + (tx * 4 + 3) * QS_LD;

    for (int j0 = 0; j0 <= q0; j0 += 64) {
        __syncthreads();
        for (int f = tid; f < 2048; f += 256) {
            const int r = f >> 5, c = (f & 31) << 2;
            float4 v = *(const float4*)(Kg + ((size_t)((b * SS + j0 + r) * NG + g)) * HD + c);
            float* d = Ks + r * QS_LD + c;
            d[0] = v.x; d[1] = v.y; d[2] = v.z; d[3] = v.w;
        }
        __syncthreads();

        float acc[4][4];
#pragma unroll
        for (int i = 0; i < 4; ++i)
#pragma unroll
            for (int j = 0; j < 4; ++j) acc[i][j] = 0.f;

#pragma unroll 4
        for (int d = 0; d < HD; ++d) {
            const float a0 = q_r0[d], a1 = q_r1[d], a2 = q_r2[d], a3 = q_r3[d];
            const float b0 = k_r0[d], b1 = k_r1[d], b2 = k_r2[d], b3 = k_r3[d];
            acc[0][0] = fmaf(a0, b0, acc[0][0]); acc[0][1] = fmaf(a0, b1, acc[0][1]);
            acc[0][2] = fmaf(a0, b2, acc[0][2]); acc[0][3] = fmaf(a0, b3, acc[0][3]);
            acc[1][0] = fmaf(a1, b0, acc[1][0]); acc[1][1] = fmaf(a1, b1, acc[1][1]);
            acc[1][2] = fmaf(a1, b2, acc[1][2]); acc[1][3] = fmaf(a1, b3, acc[1][3]);
            acc[2][0] = fmaf(a2, b0, acc[2][0]); acc[2][1] = fmaf(a2, b1, acc[2][1]);
            acc[2][2] = fmaf(a2, b2, acc[2][2]); acc[2][3] = fmaf(a2, b3, acc[2][3]);
            acc[3][0] = fmaf(a3, b0, acc[3][0]); acc[3][1] = fmaf(a3, b1, acc[3][1]);
            acc[3][2] = fmaf(a3, b2, acc[3][2]); acc[3][3] = fmaf(a3, b3, acc[3][3]);
        }

        if (j0 == q0) {
#pragma unroll
            for (int i = 0; i < 4; ++i)
#pragma unroll
                for (int j = 0; j < 4; ++j)
                    if (tx * 4 + j > ty * 4 + i) acc[i][j] = -1e30f;
        }

#pragma unroll
        for (int i = 0; i < 4; ++i) {
            float mx = fmaxf(fmaxf(acc[i][0], acc[i][1]), fmaxf(acc[i][2], acc[i][3]));
#pragma unroll
            for (int o = 8; o; o >>= 1)
                mx = fmaxf(mx, __shfl_xor_sync(0xffffffffu, mx, o, 16));
            const float mnew = fmaxf(m_run[i], mx);
            const float corr = __expf(m_run[i] - mnew);
            float rs = 0.f;
#pragma unroll
            for (int j = 0; j < 4; ++j) {
                const float p = __expf(acc[i][j] - mnew);
                acc[i][j] = p; rs += p;
            }
#pragma unroll
            for (int o = 8; o; o >>= 1)
                rs += __shfl_xor_sync(0xffffffffu, rs, o, 16);
            l_run[i] = l_run[i] * corr + rs;
            m_run[i] = mnew;
#pragma unroll
            for (int c = 0; c < 8; ++c) Ob[i][c] *= corr;
            float* pp = Ps + (ty * 4 + i) * PS_LD + tx * 4;
            pp[0] = acc[i][0]; pp[1] = acc[i][1];
            pp[2] = acc[i][2]; pp[3] = acc[i][3];
        }
        __syncthreads();

        for (int f = tid; f < 2048; f += 256) {
            const int r = f >> 5, c = (f & 31) << 2;
            float4 v = *(const float4*)(Vg + ((size_t)((b * SS + j0 + r) * NG + g)) * HD + c);
            float* d = Ks + r * QS_LD + c;
            d[0] = v.x; d[1] = v.y; d[2] = v.z; d[3] = v.w;
        }
        __syncthreads();

        const float* p_r0 = Ps + (ty * 4 + 0) * PS_LD;
        const float* p_r1 = Ps + (ty * 4 + 1) * PS_LD;
        const float* p_r2 = Ps + (ty * 4 + 2) * PS_LD;
        const float* p_r3 = Ps + (ty * 4 + 3) * PS_LD;
#pragma unroll 2
        for (int j = 0; j < 64; ++j) {
            const float a0 = p_r0[j], a1 = p_r1[j], a2 = p_r2[j], a3 = p_r3[j];
            const float* vrow = Ks + j * QS_LD + tx;
#pragma unroll
            for (int c = 0; c < 8; ++c) {
                const float vv = vrow[c << 4];
                Ob[0][c] = fmaf(a0, vv, Ob[0][c]);
                Ob[1][c] = fmaf(a1, vv, Ob[1][c]);
                Ob[2][c] = fmaf(a2, vv, Ob[2][c]);
                Ob[3][c] = fmaf(a3, vv, Ob[3][c]);
            }
        }
    }

#pragma unroll
    for (int i = 0; i < 4; ++i) {
        const float inv = 1.0f / l_run[i];
        float* base = ctx + ((size_t)((b * SS + q0 + ty * 4 + i) * NH + h)) * HD + tx;
#pragma unroll
        for (int c = 0; c < 8; ++c) base[c << 4] = Ob[i][c] * inv;
    }
}

// ---------------------------------------------------------------------------
// kernel_launch
// ---------------------------------------------------------------------------
extern "C" void kernel_launch(void* const* d_in, const int* in_sizes, int n_in,
                              void* d_out, int out_size)
{
    (void)in_sizes; (void)n_in; (void)out_size;
    const float* x  = (const float*)d_in[0];
    const float* Wq = (const float*)d_in[1];
    const float* bq = (const float*)d_in[2];
    const float* Wk = (const float*)d_in[3];
    const float* bk = (const float*)d_in[4];
    const float* Wv = (const float*)d_in[5];
    const float* bv = (const float*)d_in[6];
    const float* Wo = (const float*)d_in[7];
    const float* bo = (const float*)d_in[8];
    const float* q_scale = (const float*)d_in[9];
    const float* k_scale = (const float*)d_in[10];
    float* out = (float*)d_out;

    float *gq, *gk, *gv, *gc;
    cudaGetSymbolAddress((void**)&gq, g_q);
    cudaGetSymbolAddress((void**)&gk, g_k);
    cudaGetSymbolAddress((void**)&gv, g_v);
    cudaGetSymbolAddress((void**)&gc, g_ctx);

    cudaFuncSetAttribute(attn_kernel,
                         cudaFuncAttributeMaxDynamicSharedMemorySize, ATTN_SMEM);

    const dim3 blk(256);

    // Projections (tf32 tensor cores)
    mm_tf32_kernel<<<dim3(DD / 128, MROWS / 128), blk>>>(x, Wq, bq, gq, MROWS, DD, DD);
    mm_tf32_kernel<<<dim3((NG * HD) / 128, MROWS / 128), blk>>>(x, Wk, bk, gk, MROWS, NG * HD, DD);
    mm_tf32_kernel<<<dim3((NG * HD) / 128, MROWS / 128), blk>>>(x, Wv, bv, gv, MROWS, NG * HD, DD);

    // RMSNorm + RoPE (q gets the combined 1/hd logit scale folded in)
    norm_rope_kernel<<<(MROWS * NH) / 8, blk>>>(gq, q_scale, NH, 1.0f / 128.0f);
    norm_rope_kernel<<<(MROWS * NG) / 8, blk>>>(gk, k_scale, NG, 1.0f);

    // Causal GQA attention
    attn_kernel<<<dim3(SS / 64, NH, BB), blk, ATTN_SMEM>>>(gq, gk, gv, gc);

    // Output projection (tf32 tensor cores)
    mm_tf32_kernel<<<dim3(DD / 128, MROWS / 128), blk>>>(gc, Wo, bo, out, MROWS, DD, DD);
}

// round 13
// speedup vs baseline: 4.0031x; 4.0031x over previous
#include <cuda_runtime.h>
#include <cuda_bf16.h>
#include <math.h>
#include <stdint.h>

// ---------------------------------------------------------------------------
// Problem constants
//   b=16, s=512, d=2048, H=16 heads, hd=128, G=4 kv groups, P=4 heads/group
// ---------------------------------------------------------------------------
#define BB 16
#define SS 512
#define DD 2048
#define NH 16
#define HD 128
#define NG 4
#define MROWS (BB * SS)          // 8192
#define KVD (NG * HD)            // 512

// Scratch (device globals: allocation-free rule)
__device__ float g_q[MROWS * DD];          // (b,s,H,hd) = 64MB
__device__ float g_k[MROWS * KVD];         // 16MB
__device__ float g_v[MROWS * KVD];         // 16MB
__device__ float g_ctx[MROWS * DD];        // 64MB

// ---------------------------------------------------------------------------
// tf32 helpers (compile+run proven on this harness in R4)
// ---------------------------------------------------------------------------
__device__ __forceinline__ uint32_t f2tf32(float f) {
    uint32_t u;
    asm("cvt.rna.tf32.f32 %0, %1;" : "=r"(u) : "f"(f));
    return u;
}

__device__ __forceinline__ void mma1688(float* c, const uint32_t* a, const uint32_t* b) {
    asm volatile(
        "mma.sync.aligned.m16n8k8.row.col.f32.tf32.tf32.f32 "
        "{%0,%1,%2,%3}, {%4,%5,%6,%7}, {%8,%9}, {%0,%1,%2,%3};"
        : "+f"(c[0]), "+f"(c[1]), "+f"(c[2]), "+f"(c[3])
        : "r"(a[0]), "r"(a[1]), "r"(a[2]), "r"(a[3]), "r"(b[0]), "r"(b[1]));
}

__device__ __forceinline__ uint32_t smem_u32(const void* p) {
    uint32_t a;
    asm("{ .reg .u64 t; cvta.to.shared.u64 t, %1; cvt.u32.u64 %0, t; }"
        : "=r"(a) : "l"(p));
    return a;
}

__device__ __forceinline__ void cp_async16(uint32_t dst, const void* src) {
    asm volatile("cp.async.cg.shared.global [%0], [%1], 16;"
                 :: "r"(dst), "l"(src));
}
#define CP_COMMIT()  asm volatile("cp.async.commit_group;" ::: "memory")
#define CP_WAIT(n)   asm volatile("cp.async.wait_group %0;" :: "n"(n) : "memory")

// ---------------------------------------------------------------------------
// TF32 tensor-core GEMM: C[M,N] = A[M,K] @ W[K,N] + bias[N]  (all row-major)
// W is used UNTRANSPOSED (staged n-contiguous per k-row).
// Block tile 128x128, BK=16, 256 threads (8 warps as 2x4), warp tile 64x32.
// A smem [128][20]  (stride 20 -> conflict-free scalar fragment LDS)
// B smem [16][136]  (stride 136 -> conflict-free scalar fragment LDS)
// Double-buffered cp.async. M%128==0, N%128==0, K%16==0 for all calls.
// ---------------------------------------------------------------------------
#define ALD 20
#define BLD 136

__global__ __launch_bounds__(256, 2)
void tf32_gemm(const float* __restrict__ A, const float* __restrict__ W,
               const float* __restrict__ bias, float* __restrict__ C,
               int M, int N, int K)
{
    __shared__ float As[2][128 * ALD];   // 2 x 10240B
    __shared__ float Bs[2][16 * BLD];    // 2 x  8704B

    const int tid  = threadIdx.x;
    const int lane = tid & 31;
    const int w    = tid >> 5;
    const int wm   = w >> 2;            // 0..1 (M dir, 64 rows)
    const int wn   = w & 3;             // 0..3 (N dir, 32 cols)
    const int g    = lane >> 2;         // mma groupID 0..7
    const int t    = lane & 3;          // mma thread-in-group 0..3
    const int m0   = blockIdx.y << 7;
    const int n0   = blockIdx.x << 7;

    // ---- staging maps ----
    // A: row sr (0..127), two float4 at cols sc, sc+4 (sc in {0,8})
    const int a_sr = tid >> 1;
    const int a_sc = (tid & 1) << 3;
    const float* Ag = A + (size_t)(m0 + a_sr) * K + a_sc;
    const uint32_t a_dst = smem_u32(&As[0][a_sr * ALD + a_sc]);
    // B: k-row kr (0..15), two float4 at cols bc, bc+4 (bc = (tid&15)*8)
    const int b_kr = tid >> 4;
    const int b_bc = (tid & 15) << 3;
    const float* Bg = W + (size_t)b_kr * N + n0 + b_bc;
    const uint32_t b_dst = smem_u32(&Bs[0][b_kr * BLD + b_bc]);
    const uint32_t buf_a = 128 * ALD * 4;   // byte stride between A buffers
    const uint32_t buf_b = 16 * BLD * 4;

    float acc[4][4][4];
#pragma unroll
    for (int i = 0; i < 4; ++i)
#pragma unroll
        for (int j = 0; j < 4; ++j)
#pragma unroll
            for (int r = 0; r < 4; ++r) acc[i][j][r] = 0.f;

    const int NC = K >> 4;

    // prologue
    cp_async16(a_dst,      Ag);
    cp_async16(a_dst + 16, Ag + 4);
    cp_async16(b_dst,      Bg);
    cp_async16(b_dst + 16, Bg + 4);
    CP_COMMIT();

    for (int c = 0; c < NC; ++c) {
        if (c + 1 < NC) {
            const int nb = (c + 1) & 1;
            const int k0 = (c + 1) << 4;
            cp_async16(a_dst + nb * buf_a,      Ag + k0);
            cp_async16(a_dst + nb * buf_a + 16, Ag + k0 + 4);
            cp_async16(b_dst + nb * buf_b,      Bg + (size_t)k0 * N);
            cp_async16(b_dst + nb * buf_b + 16, Bg + (size_t)k0 * N + 4);
            CP_COMMIT();
            CP_WAIT(1);
        } else {
            CP_WAIT(0);
        }
        __syncthreads();

        const float* Ab = As[c & 1];
        const float* Bb = Bs[c & 1];
#pragma unroll
        for (int ks = 0; ks < 2; ++ks) {
            const int kb = ks * 8 + t;
            uint32_t af[4][4], bf[4][2];
#pragma unroll
            for (int i = 0; i < 4; ++i) {
                const int r = wm * 64 + i * 16 + g;
                af[i][0] = f2tf32(Ab[r * ALD + kb]);
                af[i][1] = f2tf32(Ab[(r + 8) * ALD + kb]);
                af[i][2] = f2tf32(Ab[r * ALD + kb + 4]);
                af[i][3] = f2tf32(Ab[(r + 8) * ALD + kb + 4]);
            }
#pragma unroll
            for (int j = 0; j < 4; ++j) {
                const int n = wn * 32 + j * 8 + g;
                bf[j][0] = f2tf32(Bb[kb * BLD + n]);
                bf[j][1] = f2tf32(Bb[(kb + 4) * BLD + n]);
            }
#pragma unroll
            for (int i = 0; i < 4; ++i)
#pragma unroll
                for (int j = 0; j < 4; ++j)
                    mma1688(acc[i][j], af[i], bf[j]);
        }
        __syncthreads();
    }

    // epilogue: bias + store (c0,c1 -> row g cols 2t,2t+1; c2,c3 -> row g+8)
#pragma unroll
    for (int j = 0; j < 4; ++j) {
        const int col = n0 + wn * 32 + j * 8 + t * 2;
        const float2 bs = *(const float2*)&bias[col];
#pragma unroll
        for (int i = 0; i < 4; ++i) {
            const int row = m0 + wm * 64 + i * 16 + g;
            float2 v0, v1;
            v0.x = acc[i][j][0] + bs.x; v0.y = acc[i][j][1] + bs.y;
            v1.x = acc[i][j][2] + bs.x; v1.y = acc[i][j][3] + bs.y;
            *(float2*)&C[(size_t)row * N + col]       = v0;
            *(float2*)&C[(size_t)(row + 8) * N + col] = v1;
        }
    }
}

// ---------------------------------------------------------------------------
// RMSNorm + RoPE (unchanged, passing)
// ---------------------------------------------------------------------------
__global__ __launch_bounds__(256)
void norm_rope_kernel(float* __restrict__ X, const float* __restrict__ scale,
                      int nh, float extra)
{
    const int warp = threadIdx.x >> 5;
    const int lane = threadIdx.x & 31;
    const int row  = blockIdx.x * 8 + warp;
    const int t    = (row / nh) & (SS - 1);

    float* p = X + (size_t)row * HD + lane * 4;
    float4 v = *(float4*)p;

    float ss = v.x * v.x + v.y * v.y + v.z * v.z + v.w * v.w;
#pragma unroll
    for (int o = 16; o; o >>= 1) ss += __shfl_xor_sync(0xffffffffu, ss, o);
    const float r = rsqrtf(ss * (1.0f / 128.0f) + 1e-6f);

    float4 sc = *(const float4*)(scale + lane * 4);
    float y0 = v.x * r * sc.x;
    float y1 = v.y * r * sc.y;
    float y2 = v.z * r * sc.z;
    float y3 = v.w * r * sc.w;

    const int i0 = lane * 2;
    const float LN1E4 = 9.2103403719761836f;
    float f0 = expf(-((float)(2 * i0)     * (1.0f / 128.0f)) * LN1E4);
    float f1 = expf(-((float)(2 * i0 + 2) * (1.0f / 128.0f)) * LN1E4);
    float s0, c0, s1, c1;
    sincosf((float)t * f0, &s0, &c0);
    sincosf((float)t * f1, &s1, &c1);

    float4 o;
    o.x = (y0 * c0 - y1 * s0) * extra;
    o.y = (y0 * s0 + y1 * c0) * extra;
    o.z = (y2 * c1 - y3 * s1) * extra;
    o.w = (y2 * s1 + y3 * c1) * extra;
    *(float4*)p = o;
}

// ---------------------------------------------------------------------------
// Causal flash attention, fp32 (unchanged, passing)
// ---------------------------------------------------------------------------
#define QS_LD 129
#define PS_LD 68
#define ATTN_SMEM ((2 * 64 * QS_LD + 64 * PS_LD) * 4)   // 83456 bytes

__global__ __launch_bounds__(256)
void attn_kernel(const float* __restrict__ Q, const float* __restrict__ Kg,
                 const float* __restrict__ Vg, float* __restrict__ ctx)
{
    extern __shared__ float smf[];
    float* Qs = smf;
    float* Ks = smf + 64 * QS_LD;
    float* Ps = smf + 2 * 64 * QS_LD;

    const int tid = threadIdx.x;
    const int tx  = tid & 15;
    const int ty  = tid >> 4;
    const int q0  = blockIdx.x << 6;
    const int h   = blockIdx.y;
    const int b   = blockIdx.z;
    const int g   = h >> 2;

    for (int f = tid; f < 2048; f += 256) {
        const int r = f >> 5, c = (f & 31) << 2;
        float4 v = *(const float4*)(Q + ((size_t)((b * SS + q0 + r) * NH + h)) * HD + c);
        float* d = Qs + r * QS_LD + c;
        d[0] = v.x; d[1] = v.y; d[2] = v.z; d[3] = v.w;
    }

    float m_run[4], l_run[4], Ob[4][8];
#pragma unroll
    for (int i = 0; i < 4; ++i) {
        m_run[i] = -1e30f; l_run[i] = 0.f;
#pragma unroll
        for (int c = 0; c < 8; ++c) Ob[i][c] = 0.f;
    }

    const float* q_r0 = Qs + (ty * 4 + 0) * QS_LD;
    const float* q_r1 = Qs + (ty * 4 + 1) * QS_LD;
    const float* q_r2 = Qs + (ty * 4 + 2) * QS_LD;
    const float* q_r3 = Qs + (ty * 4 + 3) * QS_LD;
    const float* k_r0 = Ks + (tx * 4 + 0) * QS_LD;
    const float* k_r1 = Ks + (tx * 4 + 1) * QS_LD;
    const float* k_r2 = Ks + (tx * 4 + 2) * QS_LD;
    const float* k_r3 = Ks + (tx * 4 + 3) * QS_LD;

    for (int j0 = 0; j0 <= q0; j0 += 64) {
        __syncthreads();
        for (int f = tid; f < 2048; f += 256) {
            const int r = f >> 5, c = (f & 31) << 2;
            float4 v = *(const float4*)(Kg + ((size_t)((b * SS + j0 + r) * NG + g)) * HD + c);
            float* d = Ks + r * QS_LD + c;
            d[0] = v.x; d[1] = v.y; d[2] = v.z; d[3] = v.w;
        }
        __syncthreads();

        float acc[4][4];
#pragma unroll
        for (int i = 0; i < 4; ++i)
#pragma unroll
            for (int j = 0; j < 4; ++j) acc[i][j] = 0.f;

#pragma unroll 4
        for (int d = 0; d < HD; ++d) {
            const float a0 = q_r0[d], a1 = q_r1[d], a2 = q_r2[d], a3 = q_r3[d];
            const float b0 = k_r0[d], b1 = k_r1[d], b2 = k_r2[d], b3 = k_r3[d];
            acc[0][0] = fmaf(a0, b0, acc[0][0]); acc[0][1] = fmaf(a0, b1, acc[0][1]);
            acc[0][2] = fmaf(a0, b2, acc[0][2]); acc[0][3] = fmaf(a0, b3, acc[0][3]);
            acc[1][0] = fmaf(a1, b0, acc[1][0]); acc[1][1] = fmaf(a1, b1, acc[1][1]);
            acc[1][2] = fmaf(a1, b2, acc[1][2]); acc[1][3] = fmaf(a1, b3, acc[1][3]);
            acc[2][0] = fmaf(a2, b0, acc[2][0]); acc[2][1] = fmaf(a2, b1, acc[2][1]);
            acc[2][2] = fmaf(a2, b2, acc[2][2]); acc[2][3] = fmaf(a2, b3, acc[2][3]);
            acc[3][0] = fmaf(a3, b0, acc[3][0]); acc[3][1] = fmaf(a3, b1, acc[3][1]);
            acc[3][2] = fmaf(a3, b2, acc[3][2]); acc[3][3] = fmaf(a3, b3, acc[3][3]);
        }

        if (j0 == q0) {
#pragma unroll
            for (int i = 0; i < 4; ++i)
#pragma unroll
                for (int j = 0; j < 4; ++j)
                    if (tx * 4 + j > ty * 4 + i) acc[i][j] = -1e30f;
        }

#pragma unroll
        for (int i = 0; i < 4; ++i) {
            float mx = fmaxf(fmaxf(acc[i][0], acc[i][1]), fmaxf(acc[i][2], acc[i][3]));
#pragma unroll
            for (int o = 8; o; o >>= 1)
                mx = fmaxf(mx, __shfl_xor_sync(0xffffffffu, mx, o, 16));
            const float mnew = fmaxf(m_run[i], mx);
            const float corr = __expf(m_run[i] - mnew);
            float rs = 0.f;
#pragma unroll
            for (int j = 0; j < 4; ++j) {
                const float p = __expf(acc[i][j] - mnew);
                acc[i][j] = p; rs += p;
            }
#pragma unroll
            for (int o = 8; o; o >>= 1)
                rs += __shfl_xor_sync(0xffffffffu, rs, o, 16);
            l_run[i] = l_run[i] * corr + rs;
            m_run[i] = mnew;
#pragma unroll
            for (int c = 0; c < 8; ++c) Ob[i][c] *= corr;
            float* pp = Ps + (ty * 4 + i) * PS_LD + tx * 4;
            pp[0] = acc[i][0]; pp[1] = acc[i][1];
            pp[2] = acc[i][2]; pp[3] = acc[i][3];
        }
        __syncthreads();

        for (int f = tid; f < 2048; f += 256) {
            const int r = f >> 5, c = (f & 31) << 2;
            float4 v = *(const float4*)(Vg + ((size_t)((b * SS + j0 + r) * NG + g)) * HD + c);
            float* d = Ks + r * QS_LD + c;
            d[0] = v.x; d[1] = v.y; d[2] = v.z; d[3] = v.w;
        }
        __syncthreads();

        const float* p_r0 = Ps + (ty * 4 + 0) * PS_LD;
        const float* p_r1 = Ps + (ty * 4 + 1) * PS_LD;
        const float* p_r2 = Ps + (ty * 4 + 2) * PS_LD;
        const float* p_r3 = Ps + (ty * 4 + 3) * PS_LD;
#pragma unroll 2
        for (int j = 0; j < 64; ++j) {
            const float a0 = p_r0[j], a1 = p_r1[j], a2 = p_r2[j], a3 = p_r3[j];
            const float* vrow = Ks + j * QS_LD + tx;
#pragma unroll
            for (int c = 0; c < 8; ++c) {
                const float vv = vrow[c << 4];
                Ob[0][c] = fmaf(a0, vv, Ob[0][c]);
                Ob[1][c] = fmaf(a1, vv, Ob[1][c]);
                Ob[2][c] = fmaf(a2, vv, Ob[2][c]);
                Ob[3][c] = fmaf(a3, vv, Ob[3][c]);
            }
        }
    }

#pragma unroll
    for (int i = 0; i < 4; ++i) {
        const float inv = 1.0f / l_run[i];
        float* base = ctx + ((size_t)((b * SS + q0 + ty * 4 + i) * NH + h)) * HD + tx;
#pragma unroll
        for (int c = 0; c < 8; ++c) base[c << 4] = Ob[i][c] * inv;
    }
}

// ---------------------------------------------------------------------------
// kernel_launch
// ---------------------------------------------------------------------------
extern "C" void kernel_launch(void* const* d_in, const int* in_sizes, int n_in,
                              void* d_out, int out_size)
{
    (void)in_sizes; (void)n_in; (void)out_size;
    const float* x  = (const float*)d_in[0];
    const float* Wq = (const float*)d_in[1];
    const float* bq = (const float*)d_in[2];
    const float* Wk = (const float*)d_in[3];
    const float* bk = (const float*)d_in[4];
    const float* Wv = (const float*)d_in[5];
    const float* bv = (const float*)d_in[6];
    const float* Wo = (const float*)d_in[7];
    const float* bo = (const float*)d_in[8];
    const float* q_scale = (const float*)d_in[9];
    const float* k_scale = (const float*)d_in[10];
    float* out = (float*)d_out;

    float *gq, *gk, *gv, *gc;
    cudaGetSymbolAddress((void**)&gq, g_q);
    cudaGetSymbolAddress((void**)&gk, g_k);
    cudaGetSymbolAddress((void**)&gv, g_v);
    cudaGetSymbolAddress((void**)&gc, g_ctx);

    cudaFuncSetAttribute(attn_kernel,
                         cudaFuncAttributeMaxDynamicSharedMemorySize, ATTN_SMEM);

    const dim3 blk(256);

    // Projections (tf32 mma, W used untransposed)
    tf32_gemm<<<dim3(DD / 128, MROWS / 128), blk>>>(x, Wq, bq, gq, MROWS, DD, DD);
    tf32_gemm<<<dim3(KVD / 128, MROWS / 128), blk>>>(x, Wk, bk, gk, MROWS, KVD, DD);
    tf32_gemm<<<dim3(KVD / 128, MROWS / 128), blk>>>(x, Wv, bv, gv, MROWS, KVD, DD);

    // RMSNorm + RoPE (q gets combined 1/hd logit scale folded in)
    norm_rope_kernel<<<(MROWS * NH) / 8, blk>>>(gq, q_scale, NH, 1.0f / 128.0f);
    norm_rope_kernel<<<(MROWS * NG) / 8, blk>>>(gk, k_scale, NG, 1.0f);

    // Causal GQA attention
    attn_kernel<<<dim3(SS / 64, NH, BB), blk, ATTN_SMEM>>>(gq, gk, gv, gc);

    // Output projection
    tf32_gemm<<<dim3(DD / 128, MROWS / 128), blk>>>(gc, Wo, bo, out, MROWS, DD, DD);
}